// round 4
// baseline (speedup 1.0000x reference)
#include <cuda_runtime.h>

#define Nn 2048
#define SEG 64
#define WARPS 8
#define PITCH (Nn + Nn/64)           /* 2080 floats, swizzled row pitch */
#define SMEM_FLOATS (2*PITCH + WARPS*PITCH)
#define SMEM_BYTES (SMEM_FLOATS*4)   /* 83200 bytes */

__device__ float2 g_cs[Nn];

__global__ void cs_kernel(const float* __restrict__ angles) {
    int i = blockIdx.x * blockDim.x + threadIdx.x;
    if (i < Nn) {
        float a = angles[i];
        float2 v; v.x = cosf(a); v.y = sinf(a);
        g_cs[i] = v;
    }
}

// y[b,:] = R x[b,:] with R = G_0 G_1 ... G_{n-1}; apply rotations k = n-1 .. 0.
// Affine recurrence: u_{t+1} = c_k*x'[k] - s_k*u_t  (k = n-1-t), u_0 = x[0],
// x'[0] = s_{n-1} x[n-1] + c_{n-1} x[0], x'[k]=x[k] otherwise.
// Outputs: y[k+1] = s_k*x'[k] + c_k*u_t for t>=1;  y[0] = u_n.
__global__ void __launch_bounds__(WARPS*32, 2)
givens_kernel(const float* __restrict__ x, float* __restrict__ y) {
    extern __shared__ float smem[];
    float2* cs = (float2*)smem;                 // swizzled, PITCH float2
    float*  bufall = smem + 2*PITCH;            // WARPS rows, PITCH floats each

    int tid  = threadIdx.x;
    int lane = tid & 31;
    int w    = tid >> 5;

    // Stage cos/sin into smem (swizzled addressing addr(k) = k + (k>>6))
    for (int i = tid; i < Nn; i += WARPS*32) {
        cs[i + (i >> 6)] = g_cs[i];
    }

    float* buf = bufall + w * PITCH;
    long row = (long)blockIdx.x * WARPS + w;
    const float* xr = x + row * (long)Nn;

    // Coalesced float4 load of the row into swizzled smem
    for (int i = lane * 4; i < Nn; i += 128) {
        float4 v = *reinterpret_cast<const float4*>(xr + i);
        int a = i + (i >> 6);           // i multiple of 4 -> 4 slots contiguous
        buf[a]   = v.x; buf[a+1] = v.y;
        buf[a+2] = v.z; buf[a+3] = v.w;
    }
    __syncthreads();

    float u0 = buf[0];                  // x[0] (swizzled addr(0) == 0)
    if (lane == 0) {
        float2 cN = cs[Nn-1 + ((Nn-1) >> 6)];
        float xN  = buf[Nn-1 + ((Nn-1) >> 6)];
        buf[0] = cN.y * xN + cN.x * u0; // x'[0] = v0_mid
    }
    __syncwarp();

    // Lane l owns t in [64l, 64l+63]  ->  k = 2047 - t, an aligned 64-block.
    int kbase = Nn - 1 - lane * SEG;
    int base  = kbase + (kbase >> 6);   // swizzle offset constant per segment

    // ---- Pass A: compose segment affine map  u_out = A + B*u_in ----
    float A = 0.f, Bb = 1.f;
    #pragma unroll 8
    for (int p = 0; p < SEG; p++) {
        float2 c  = cs[base - p];
        float  xv = buf[base - p];
        A  = fmaf(-c.y, A, c.x * xv);   // A <- alpha + beta*A, beta = -s
        Bb = -c.y * Bb;
    }

    // ---- Warp scan of affine maps (compose current AFTER previous) ----
    #pragma unroll
    for (int d = 1; d < 32; d <<= 1) {
        float Ap = __shfl_up_sync(0xffffffffu, A,  d);
        float Bp = __shfl_up_sync(0xffffffffu, Bb, d);
        if (lane >= d) { A = fmaf(Bb, Ap, A); Bb *= Bp; }
    }
    float Ae = __shfl_up_sync(0xffffffffu, A,  1);
    float Be = __shfl_up_sync(0xffffffffu, Bb, 1);
    float u  = (lane == 0) ? u0 : fmaf(Be, u0, Ae);   // segment entry carry

    // ---- Pass B: replay, emit y[k+1] into just-freed slot k ----
    #pragma unroll 8
    for (int p = 0; p < SEG; p++) {
        float2 c  = cs[base - p];
        float  xv = buf[base - p];
        float  sx = c.y * xv;
        float  cx = c.x * xv;
        buf[base - p] = fmaf(c.x, u, sx);   // y[k+1]
        u = fmaf(-c.y, u, cx);              // carry
    }
    // Order lane0's benign p=0 overwrite of slot addr(2047) BEFORE lane31's
    // y[0] write (cross-lane same-address writes need an explicit sync point).
    __syncwarp();
    if (lane == 31) buf[Nn-1 + ((Nn-1) >> 6)] = u;    // y[0] = u_n
    __syncwarp();

    // Coalesced vector store: y[j..j+3] = buf[addr((j-1..j+2) mod N)]
    float* yr = y + row * (long)Nn;
    for (int j = lane * 4; j < Nn; j += 128) {
        float4 v;
        int k0 = (j + Nn - 1) & (Nn - 1);
        v.x = buf[k0 + (k0 >> 6)];
        int k1 = j;                     // j..j+2 < Nn, no wrap
        v.y = buf[k1 + (k1 >> 6)];
        int k2 = j + 1;
        v.z = buf[k2 + (k2 >> 6)];
        int k3 = j + 2;
        v.w = buf[k3 + (k3 >> 6)];
        *reinterpret_cast<float4*>(yr + j) = v;
    }
}

extern "C" void kernel_launch(void* const* d_in, const int* in_sizes, int n_in,
                              void* d_out, int out_size) {
    const float* x      = (const float*)d_in[0];
    const float* angles = (const float*)d_in[1];
    // Defensive: swap if metadata order is reversed
    if (n_in >= 2 && in_sizes[0] == Nn && in_sizes[1] != Nn) {
        const float* t = x; x = angles; angles = t;
    }
    float* y = (float*)d_out;

    cs_kernel<<<(Nn + 255) / 256, 256>>>(angles);

    cudaFuncSetAttribute(givens_kernel,
                         cudaFuncAttributeMaxDynamicSharedMemorySize, SMEM_BYTES);
    int rows = out_size / Nn;                 // B = 16384
    givens_kernel<<<rows / WARPS, WARPS * 32, SMEM_BYTES>>>(x, y);
}

// round 9
// speedup vs baseline: 2.2506x; 2.2506x over previous
#include <cuda_runtime.h>

#define Nn 2048
#define SEG 32
#define RPB 4                     /* rows per block */
#define THREADS (RPB*2*32)        /* 256: 2 warps per row */
#define PITCH (Nn + Nn/32)        /* 2112 floats, >>5 swizzle pitch */
#define SMEM_FLOATS (2*PITCH + RPB*PITCH + 2*RPB)
#define SMEM_BYTES (SMEM_FLOATS*4)   /* 50720 B -> 4 blocks/SM */

#define NAMED_BAR(id) asm volatile("bar.sync %0, %1;" :: "r"(id), "r"(64) : "memory")

__device__ float2 g_cs[Nn];

__global__ void cs_kernel(const float* __restrict__ angles) {
    int i = blockIdx.x * blockDim.x + threadIdx.x;
    if (i < Nn) {
        float a = angles[i];
        float2 v; v.x = cosf(a); v.y = sinf(a);
        g_cs[i] = v;
    }
}

// y = R x per row, R = G_0..G_{n-1} applied k = n-1 .. 0.
// Carry: u_{t+1} = c_k*x'[k] - s_k*u_t (k = n-1-t), u_0 = x[0],
// x'[0] = s_{n-1}x[n-1] + c_{n-1}x[0].  Outputs y[k+1] = s_k*x'[k] + c_k*u_t
// (t>=1), y[0] = u_n.  Row split across 2 warps (h=0,1), 32 segments of 32
// steps each; affine (A,B) maps scanned within warp, h0 total handed to h1.
__global__ void __launch_bounds__(THREADS, 4)
givens_kernel(const float* __restrict__ x, float* __restrict__ y) {
    extern __shared__ float smem[];
    float2* cs     = (float2*)smem;                 // PITCH float2, swizzled
    float*  bufall = smem + 2*PITCH;                // RPB row buffers
    float*  ptot   = smem + 2*PITCH + RPB*PITCH;    // per-row (A,B) of h0

    int tid  = threadIdx.x;
    int lane = tid & 31;
    int w    = tid >> 5;
    int r    = w >> 1;          // row within block
    int h    = w & 1;           // row half

    // Stage cos/sin (block-wide), swizzled addr(k) = k + (k>>5)
    for (int i = tid; i < Nn; i += THREADS)
        cs[i + (i >> 5)] = g_cs[i];

    float* buf = bufall + r * PITCH;
    long row = (long)blockIdx.x * RPB + r;
    const float* xr = x + row * (long)Nn;

    // Stage this half of the row, coalesced float4
    for (int i = h*1024 + lane*4; i < (h+1)*1024; i += 128) {
        float4 v = *reinterpret_cast<const float4*>(xr + i);
        int a = i + (i >> 5);             // i%4==0 -> 4 contiguous slots
        buf[a]   = v.x; buf[a+1] = v.y;
        buf[a+2] = v.z; buf[a+3] = v.w;
    }
    __syncthreads();                      // cs + both halves visible

    float u0 = buf[0];                    // x[0] (addr(0) == 0), all pair lanes
    NAMED_BAR(r + 1);                     // reads of buf[0] before overwrite
    if (h == 0 && lane == 0) {
        float2 cN = cs[2047 + (2047 >> 5)];
        float  xN = buf[2047 + (2047 >> 5)];
        buf[0] = cN.y * xN + cN.x * u0;   // x'[0]
    }
    NAMED_BAR(r + 1);

    int g     = h*32 + lane;              // global segment 0..63 (t order)
    int kbase = Nn - 1 - g*SEG;
    int base  = kbase + (kbase >> 5);     // swizzle offset constant in segment

    // ---- Pass A: compose segment affine map  u_out = A + B*u_in ----
    float A = 0.f, Bb = 1.f;
    #pragma unroll 8
    for (int p = 0; p < SEG; p++) {
        float2 c  = cs[base - p];
        float  xv = buf[base - p];
        A  = fmaf(-c.y, A, c.x * xv);
        Bb = -c.y * Bb;
    }

    // ---- Intra-warp inclusive scan of affine maps ----
    #pragma unroll
    for (int d = 1; d < 32; d <<= 1) {
        float Ap = __shfl_up_sync(0xffffffffu, A,  d);
        float Bp = __shfl_up_sync(0xffffffffu, Bb, d);
        if (lane >= d) { A = fmaf(Bb, Ap, A); Bb *= Bp; }
    }
    if (h == 0 && lane == 31) { ptot[2*r] = A; ptot[2*r + 1] = Bb; }
    NAMED_BAR(r + 1);

    // Entry carry: h1 pre-applies h0's total map to u0
    float v0 = u0;
    if (h == 1) v0 = fmaf(ptot[2*r + 1], u0, ptot[2*r]);
    float Ae = __shfl_up_sync(0xffffffffu, A,  1);
    float Be = __shfl_up_sync(0xffffffffu, Bb, 1);
    float u  = (lane == 0) ? v0 : fmaf(Be, v0, Ae);

    // ---- Pass B: replay, emit y[k+1] into freed slot k ----
    {   // peel p=0: segment g==0 (t=0) produces no output -> skip store,
        // leaving slot addr(2047) solely to the y[0] writer below.
        float2 c  = cs[base];
        float  xv = buf[base];
        if (g != 0) buf[base] = fmaf(c.x, u, c.y * xv);
        u = fmaf(-c.y, u, c.x * xv);
    }
    #pragma unroll 8
    for (int p = 1; p < SEG; p++) {
        float2 c  = cs[base - p];
        float  xv = buf[base - p];
        buf[base - p] = fmaf(c.x, u, c.y * xv);
        u = fmaf(-c.y, u, c.x * xv);
    }
    if (g == 63) buf[2047 + (2047 >> 5)] = u;   // y[0] = u_n
    NAMED_BAR(r + 1);

    // ---- Epilogue: coalesced float4 store, y[j] = buf[addr((j-1) mod N)] ----
    float* yr = y + row * (long)Nn;
    for (int j = h*1024 + lane*4; j < (h+1)*1024; j += 128) {
        float4 v;
        int k0 = (j + Nn - 1) & (Nn - 1);
        v.x = buf[k0 + (k0 >> 5)];
        v.y = buf[j     + (j     >> 5)];
        v.z = buf[j + 1 + ((j+1) >> 5)];
        v.w = buf[j + 2 + ((j+2) >> 5)];
        *reinterpret_cast<float4*>(yr + j) = v;
    }
}

extern "C" void kernel_launch(void* const* d_in, const int* in_sizes, int n_in,
                              void* d_out, int out_size) {
    const float* x      = (const float*)d_in[0];
    const float* angles = (const float*)d_in[1];
    if (n_in >= 2 && in_sizes[0] == Nn && in_sizes[1] != Nn) {
        const float* t = x; x = angles; angles = t;
    }
    float* y = (float*)d_out;

    cs_kernel<<<(Nn + 255) / 256, 256>>>(angles);

    cudaFuncSetAttribute(givens_kernel,
                         cudaFuncAttributeMaxDynamicSharedMemorySize, SMEM_BYTES);
    int rows = out_size / Nn;                 // B = 16384
    givens_kernel<<<rows / RPB, THREADS, SMEM_BYTES>>>(x, y);
}